// round 10
// baseline (speedup 1.0000x reference)
#include <cuda_runtime.h>
#include <cuda_bf16.h>
#include <cstdint>
#include <cstring>

#define DD 1024
#define MM 256
#define BB 2048
#define NCH 8            // 8 chunks x 128 d
#define CSTG 2112        // uint4 per c stage (64 rows x 33, odd stride)
#define CONVN 1024       // uint4 per converted-x buffer (64 rows x 16)

// Device scratch (no allocations allowed)
__device__ __align__(16) uint32_t g_cb[MM * DD];   // per d-pair: {c1 bf16x2, c0 bf16x2}
__device__ __align__(16) float g_logw[MM];
__device__ __align__(16) float g_comp[BB * MM];    // sum over d of log2(2*lik)
__device__ int g_cnt[BB / 64];                     // per-b-tile completion counters

__device__ __forceinline__ __nv_bfloat162 asbf2(uint32_t u) {
    __nv_bfloat162 r; memcpy(&r, &u, 4); return r;
}
__device__ __forceinline__ uint32_t asu32(__nv_bfloat162 b) {
    uint32_t u; memcpy(&u, &b, 4); return u;
}
__device__ __forceinline__ void cp16(uint32_t dst, const void* src) {
    asm volatile("cp.async.cg.shared.global [%0], [%1], 16;" :: "r"(dst), "l"(src));
}
__device__ __forceinline__ uint32_t packbf(float a, float b) {
    return asu32(__floats2bfloat162_rn(a, b));
}

// ---------------------------------------------------------------------------
// Prep: blocks [0,64) P->coefs (MLP8, 64 x 2048 float2 = full 256x1024 P);
// block 64: logw + counter reset.
// ---------------------------------------------------------------------------
__global__ void prep_kernel(const float* __restrict__ P,
                            const float* __restrict__ W) {
    int bk = blockIdx.x, t = threadIdx.x;
    if (bk < 64) {
        const float2* src = reinterpret_cast<const float2*>(P) + bk * 2048 + t;
        uint2* dst = reinterpret_cast<uint2*>(g_cb) + bk * 2048 + t;
        float2 v[8];
#pragma unroll
        for (int k = 0; k < 8; k++) v[k] = src[k * 256];
#pragma unroll
        for (int k = 0; k < 8; k++) {
            float c0a = 2.0f / (1.0f + __expf(v[k].x));   // 2*(1-p)
            float c0b = 2.0f / (1.0f + __expf(v[k].y));
            float c1a = 2.0f - 2.0f * c0a;                // 2*(2p-1)
            float c1b = 2.0f - 2.0f * c0b;
            uint2 w;
            w.x = packbf(c1a, c1b);
            w.y = packbf(c0a, c0b);
            dst[k * 256] = w;
        }
    } else {
        __shared__ float sh[MM];
        if (t < BB / 64) g_cnt[t] = 0;
        float w = W[t];
        sh[t] = w;
        __syncthreads();
        for (int s = MM / 2; s > 0; s >>= 1) {
            if (t < s) sh[t] = fmaxf(sh[t], sh[t + s]);
            __syncthreads();
        }
        float mx = sh[0];
        __syncthreads();
        sh[t] = expf(w - mx);
        __syncthreads();
        for (int s = MM / 2; s > 0; s >>= 1) {
            if (t < s) sh[t] += sh[t + s];
            __syncthreads();
        }
        g_logw[t] = w - (mx + logf(sh[0]));
    }
}

// ---------------------------------------------------------------------------
// Main: block 64b x 64m, 512 threads = 16(tx,m) x 16(ty,b) x 2(tz,d-split),
// thread tile 4b x 4m per half of each 128-d chunk. c streamed via 3-stage
// cp.async ring; x loaded as raw fp32 via LDG one chunk ahead, converted to
// bf16x2 in registers, staged in a double-buffered conv smem buffer. ONE
// __syncthreads per chunk. __log2f merge per chunk (64 d / accumulator).
// Last CTA per b-tile performs the 64-batch logsumexp (fused reduce).
// ---------------------------------------------------------------------------
__global__ void __launch_bounds__(512, 1) main_kernel(const float* __restrict__ x,
                                                      float* __restrict__ out) {
    extern __shared__ uint4 sm[];
    uint4* cs   = sm;                 // 3 stages x CSTG
    uint4* conv = sm + 3 * CSTG;      // 2 buffers x CONVN
    __shared__ int sflag;

    const int t  = threadIdx.x;
    const int tx = t & 15;
    const int ty = (t >> 4) & 15;
    const int tz = t >> 8;
    const int bBase = blockIdx.x * 64;
    const int mBase = blockIdx.y * 64;

    // c fetch mapping: rows 0..63, 8 quads per thread-op set
    const int cr = t >> 3, cq = t & 7;
    const uint32_t* csrc = g_cb + (size_t)(mBase + cr) * DD + cq * 4;
    const uint32_t cd = (uint32_t)__cvta_generic_to_shared(&cs[cr * 33 + cq]);

    auto issueC = [&](int ck, int slot) {
        const uint32_t* cp = csrc + ck * 128;
        uint32_t cb = cd + slot * CSTG * 16;
        cp16(cb,           cp);
        cp16(cb + 8 * 16,  cp + 32);
        cp16(cb + 16 * 16, cp + 64);
        cp16(cb + 24 * 16, cp + 96);
        asm volatile("cp.async.commit_group;");
    };

    // x mapping: thread produces conv[t] (row = t>>4, d-octet q = t&15) and
    // conv[t+512] (row+32, same q)
    const int xrow = t >> 4, xqo = t & 15;
    const float* xp0 = x + (size_t)(bBase + xrow) * DD + xqo * 8;
    const float* xp1 = xp0 + (size_t)32 * DD;

    float4 f0, f1, f2, f3;
    auto ldgX = [&](int ck) {
        const float4* a = reinterpret_cast<const float4*>(xp0 + ck * 128);
        const float4* b = reinterpret_cast<const float4*>(xp1 + ck * 128);
        f0 = a[0]; f1 = a[1]; f2 = b[0]; f3 = b[1];
    };
    auto convX = [&](int buf) {
        uint4 o0, o1;
        o0.x = packbf(f0.x, f0.y); o0.y = packbf(f0.z, f0.w);
        o0.z = packbf(f1.x, f1.y); o0.w = packbf(f1.z, f1.w);
        o1.x = packbf(f2.x, f2.y); o1.y = packbf(f2.z, f2.w);
        o1.z = packbf(f3.x, f3.y); o1.w = packbf(f3.z, f3.w);
        conv[buf * CONVN + t]       = o0;
        conv[buf * CONVN + t + 512] = o1;
    };

    // prologue
    ldgX(0);
    issueC(0, 0);
    issueC(1, 1);
    convX(0);
    ldgX(1);

    const uint32_t ONE2 = 0x3F803F80u;   // bf16x2 {1.0, 1.0}
    float acc[4][4];
#pragma unroll
    for (int i = 0; i < 4; i++)
#pragma unroll
        for (int jm = 0; jm < 4; jm++) acc[i][jm] = 0.0f;

    for (int ck = 0; ck < NCH; ck++) {
        asm volatile("cp.async.wait_group 1;");
        __syncthreads();                       // c[ck] + conv[ck&1] visible
        if (ck + 2 < NCH) issueC(ck + 2, (ck + 2) % 3);
        else asm volatile("cp.async.commit_group;");

        const uint4* xb = conv + (ck & 1) * CONVN + ty * 16 + tz * 8;
        const uint4* cb = cs + (ck % 3) * CSTG + tx * 33 + tz * 16;

        __nv_bfloat162 prod[4][4];
#pragma unroll
        for (int i = 0; i < 4; i++)
#pragma unroll
            for (int jm = 0; jm < 4; jm++) prod[i][jm] = asbf2(ONE2);

#pragma unroll
        for (int jq = 0; jq < 8; jq++) {       // 8 d per jq (per tz half)
            uint4 xv[4];
#pragma unroll
            for (int i = 0; i < 4; i++) xv[i] = xb[i * 16 * 16 + jq];
#pragma unroll
            for (int jm = 0; jm < 4; jm++) {
                uint4 c0 = cb[jm * 16 * 33 + jq * 2];
                uint4 c1 = cb[jm * 16 * 33 + jq * 2 + 1];
#pragma unroll
                for (int i = 0; i < 4; i++) {
                    __nv_bfloat162 l0 = __hfma2(asbf2(c0.x), asbf2(xv[i].x), asbf2(c0.y));
                    __nv_bfloat162 l1 = __hfma2(asbf2(c0.z), asbf2(xv[i].y), asbf2(c0.w));
                    __nv_bfloat162 l2 = __hfma2(asbf2(c1.x), asbf2(xv[i].z), asbf2(c1.y));
                    __nv_bfloat162 l3 = __hfma2(asbf2(c1.z), asbf2(xv[i].w), asbf2(c1.w));
                    prod[i][jm] = __hmul2(prod[i][jm],
                                          __hmul2(__hmul2(l0, l1), __hmul2(l2, l3)));
                }
            }
        }
        // merge (64 d per accumulator, scaled x2: safe fp32 range)
#pragma unroll
        for (int i = 0; i < 4; i++)
#pragma unroll
            for (int jm = 0; jm < 4; jm++) {
                uint32_t u = asu32(prod[i][jm]);
                float hi = __uint_as_float(u & 0xFFFF0000u);
                float lo = __uint_as_float(u << 16);
                acc[i][jm] += __log2f(hi * lo);
            }
        // stage next x chunk
        if (ck + 1 < NCH) convX((ck + 1) & 1);
        if (ck + 2 < NCH) ldgX(ck + 2);
    }

    asm volatile("cp.async.wait_group 0;");
    __syncthreads();
    // combine tz halves through smem (stride 17 floats: conflict-free)
    float* sh = (float*)sm;
    const int tid256 = t & 255;
    if (tz == 1) {
#pragma unroll
        for (int i = 0; i < 4; i++)
#pragma unroll
            for (int jm = 0; jm < 4; jm++)
                sh[tid256 * 17 + i * 4 + jm] = acc[i][jm];
    }
    __syncthreads();
    if (tz == 0) {
#pragma unroll
        for (int i = 0; i < 4; i++)
#pragma unroll
            for (int jm = 0; jm < 4; jm++) {
                float a = acc[i][jm] + sh[tid256 * 17 + i * 4 + jm];
                g_comp[(size_t)(bBase + ty + 16 * i) * MM + (mBase + tx + 16 * jm)] = a;
            }
    }

    // ---- fused logsumexp: last CTA of this b-tile reduces its 64 batches ----
    __threadfence();
    __syncthreads();
    if (t == 0) sflag = atomicAdd(&g_cnt[blockIdx.x], 1);
    __syncthreads();
    if (sflag == 3) {
        __threadfence();
        const float LN2 = 0.69314718055994531f;
        int warp = t >> 5, lane = t & 31;
        const float4* lw4 = reinterpret_cast<const float4*>(g_logw) + lane * 2;
        float4 l0 = lw4[0], l1 = lw4[1];
#pragma unroll
        for (int bb = 0; bb < 4; bb++) {
            int b = bBase + warp * 4 + bb;
            const float4* cp4 = reinterpret_cast<const float4*>(g_comp + (size_t)b * MM) + lane * 2;
            float4 c0 = __ldcg(cp4), c1 = __ldcg(cp4 + 1);
            float v[8];
            v[0] = (c0.x - 1024.0f) * LN2 + l0.x;
            v[1] = (c0.y - 1024.0f) * LN2 + l0.y;
            v[2] = (c0.z - 1024.0f) * LN2 + l0.z;
            v[3] = (c0.w - 1024.0f) * LN2 + l0.w;
            v[4] = (c1.x - 1024.0f) * LN2 + l1.x;
            v[5] = (c1.y - 1024.0f) * LN2 + l1.y;
            v[6] = (c1.z - 1024.0f) * LN2 + l1.z;
            v[7] = (c1.w - 1024.0f) * LN2 + l1.w;
            float mx = v[0];
#pragma unroll
            for (int j = 1; j < 8; j++) mx = fmaxf(mx, v[j]);
#pragma unroll
            for (int o = 16; o > 0; o >>= 1) mx = fmaxf(mx, __shfl_xor_sync(0xFFFFFFFFu, mx, o));
            float s = 0.0f;
#pragma unroll
            for (int j = 0; j < 8; j++) s += __expf(v[j] - mx);
#pragma unroll
            for (int o = 16; o > 0; o >>= 1) s += __shfl_xor_sync(0xFFFFFFFFu, s, o);
            if (lane == 0) out[b] = mx + __logf(s);
        }
    }
}

extern "C" void kernel_launch(void* const* d_in, const int* in_sizes, int n_in,
                              void* d_out, int out_size) {
    const float* x = nullptr;
    const float* W = nullptr;
    const float* P = nullptr;
    for (int i = 0; i < n_in; i++) {
        if      (in_sizes[i] == BB * DD) x = (const float*)d_in[i];
        else if (in_sizes[i] == MM)      W = (const float*)d_in[i];
        else if (in_sizes[i] == MM * DD) P = (const float*)d_in[i];
    }

    prep_kernel<<<65, 256>>>(P, W);

    const int SMEM = (3 * CSTG + 2 * CONVN) * 16;   // 134,144 bytes
    cudaFuncSetAttribute(main_kernel, cudaFuncAttributeMaxDynamicSharedMemorySize, SMEM);
    dim3 grid(BB / 64, MM / 64);
    main_kernel<<<grid, 512, SMEM>>>(x, (float*)d_out);
}

// round 11
// speedup vs baseline: 1.0409x; 1.0409x over previous
#include <cuda_runtime.h>
#include <cuda_bf16.h>
#include <cstdint>
#include <cstring>

#define DD 1024
#define MM 256
#define BB 2048
#define NCH 8          // 8 chunks x 128 d
#define XSTG 1024      // uint4 per x stage (64 rows x 16)
#define CSTG 2112      // uint4 per c stage (64 rows x 33, odd stride)

// Device scratch (no allocations allowed)
__device__ __align__(16) uint32_t g_cb[MM * DD];          // per d-pair: {c1 bf16x2, c0 bf16x2}
__device__ __align__(16) uint32_t g_xb[BB * (DD / 2)];    // x as bf16x2 pairs
__device__ __align__(16) float g_logw[MM];
__device__ __align__(16) float g_comp[BB * MM];           // sum over d of log2(2*lik)
__device__ int g_cnt[BB / 64];                            // per-b-tile completion counters

__device__ __forceinline__ __nv_bfloat162 asbf2(uint32_t u) {
    __nv_bfloat162 r; memcpy(&r, &u, 4); return r;
}
__device__ __forceinline__ uint32_t asu32(__nv_bfloat162 b) {
    uint32_t u; memcpy(&u, &b, 4); return u;
}
__device__ __forceinline__ void cp16(uint32_t dst, const void* src) {
    asm volatile("cp.async.ca.shared.global [%0], [%1], 16;" :: "r"(dst), "l"(src));
}
__device__ __forceinline__ uint32_t packbf(float a, float b) {
    return asu32(__floats2bfloat162_rn(a, b));
}

// ---------------------------------------------------------------------------
// Fused prep: blocks [0,256) x->bf16 (MLP8 loads, STG.128 stores);
// [256,320) P->coefs (MLP8); block 320: logw + counter reset.
// ---------------------------------------------------------------------------
__global__ void prep_kernel(const float* __restrict__ x,
                            const float* __restrict__ P,
                            const float* __restrict__ W) {
    int bk = blockIdx.x, t = threadIdx.x;
    if (bk < 256) {
        const float4* src = reinterpret_cast<const float4*>(x) + bk * 2048;
        uint4* dst = reinterpret_cast<uint4*>(g_xb) + bk * 1024;
        float4 v[4][2];
#pragma unroll
        for (int k = 0; k < 4; k++) {
            v[k][0] = src[k * 512 + t * 2];
            v[k][1] = src[k * 512 + t * 2 + 1];
        }
#pragma unroll
        for (int k = 0; k < 4; k++) {
            uint4 w;
            w.x = packbf(v[k][0].x, v[k][0].y);
            w.y = packbf(v[k][0].z, v[k][0].w);
            w.z = packbf(v[k][1].x, v[k][1].y);
            w.w = packbf(v[k][1].z, v[k][1].w);
            dst[k * 256 + t] = w;
        }
    } else if (bk < 320) {
        int b2 = bk - 256;
        const float2* src = reinterpret_cast<const float2*>(P) + b2 * 2048 + t;
        uint2* dst = reinterpret_cast<uint2*>(g_cb) + b2 * 2048 + t;
        float2 v[8];
#pragma unroll
        for (int k = 0; k < 8; k++) v[k] = src[k * 256];
#pragma unroll
        for (int k = 0; k < 8; k++) {
            float c0a = 2.0f / (1.0f + __expf(v[k].x));   // 2*(1-p)
            float c0b = 2.0f / (1.0f + __expf(v[k].y));
            float c1a = 2.0f - 2.0f * c0a;                // 2*(2p-1)
            float c1b = 2.0f - 2.0f * c0b;
            uint2 w;
            w.x = packbf(c1a, c1b);
            w.y = packbf(c0a, c0b);
            dst[k * 256] = w;
        }
    } else {
        __shared__ float sh[MM];
        if (t < BB / 64) g_cnt[t] = 0;
        float w = W[t];
        sh[t] = w;
        __syncthreads();
        for (int s = MM / 2; s > 0; s >>= 1) {
            if (t < s) sh[t] = fmaxf(sh[t], sh[t + s]);
            __syncthreads();
        }
        float mx = sh[0];
        __syncthreads();
        sh[t] = expf(w - mx);
        __syncthreads();
        for (int s = MM / 2; s > 0; s >>= 1) {
            if (t < s) sh[t] += sh[t + s];
            __syncthreads();
        }
        g_logw[t] = w - (mx + logf(sh[0]));
    }
}

// ---------------------------------------------------------------------------
// Main (R8 structure): block 64b x 64m, 512 threads = 16(tx,m) x 16(ty,b) x
// 2(tz,d-split), thread tile 4b x 4m over half of each 128-d chunk. 3-stage
// cp.async ring, ONE __syncthreads per chunk. bf16 HFMA2/HMUL2 inner;
// __log2f merge per chunk. Last CTA per b-tile does the fused logsumexp.
// ---------------------------------------------------------------------------
__global__ void __launch_bounds__(512, 1) main_kernel(float* __restrict__ out) {
    extern __shared__ uint4 sm[];
    uint4* xs = sm;                // 3 stages x XSTG
    uint4* cs = sm + 3 * XSTG;     // 3 stages x CSTG
    __shared__ int sflag;

    const int t  = threadIdx.x;
    const int tx = t & 15;
    const int ty = (t >> 4) & 15;
    const int tz = t >> 8;
    const int bBase = blockIdx.x * 64;
    const int mBase = blockIdx.y * 64;

    // fetch mappings: rows 0..63, 8 quads covered per thread-op set
    const int xr = t >> 3, xq = t & 7;
    const uint32_t* xsrc = g_xb + (size_t)(bBase + xr) * (DD / 2) + xq * 4;
    const uint32_t* csrc = g_cb + (size_t)(mBase + xr) * DD + xq * 4;
    const uint32_t xd = (uint32_t)__cvta_generic_to_shared(&xs[xr * 16 + xq]);
    const uint32_t cd = (uint32_t)__cvta_generic_to_shared(&cs[xr * 33 + xq]);

    auto issue = [&](int ck, int slot) {
        const uint32_t* xp = xsrc + ck * 64;          // 128 d = 64 uint32 per row
        uint32_t xb = xd + slot * XSTG * 16;
        cp16(xb,          xp);
        cp16(xb + 8 * 16, xp + 32);
        const uint32_t* cp = csrc + ck * 128;         // 128 d = 128 uint32 per row
        uint32_t cb = cd + slot * CSTG * 16;
        cp16(cb,           cp);
        cp16(cb + 8 * 16,  cp + 32);
        cp16(cb + 16 * 16, cp + 64);
        cp16(cb + 24 * 16, cp + 96);
        asm volatile("cp.async.commit_group;");
    };

    issue(0, 0);
    issue(1, 1);

    const uint32_t ONE2 = 0x3F803F80u;   // bf16x2 {1.0, 1.0}
    float acc[4][4];
#pragma unroll
    for (int i = 0; i < 4; i++)
#pragma unroll
        for (int jm = 0; jm < 4; jm++) acc[i][jm] = 0.0f;

    for (int ck = 0; ck < NCH; ck++) {
        asm volatile("cp.async.wait_group 1;");
        __syncthreads();
        if (ck + 2 < NCH) issue(ck + 2, (ck + 2) % 3);
        else asm volatile("cp.async.commit_group;");

        const int slot = ck % 3;
        const uint4* xb = xs + slot * XSTG + ty * 16 + tz * 8;
        const uint4* cb = cs + slot * CSTG + tx * 33 + tz * 16;

        __nv_bfloat162 prod[4][4];
#pragma unroll
        for (int i = 0; i < 4; i++)
#pragma unroll
            for (int jm = 0; jm < 4; jm++) prod[i][jm] = asbf2(ONE2);

#pragma unroll
        for (int jq = 0; jq < 8; jq++) {          // 8 d per jq (per tz half)
            uint4 xv[4];
#pragma unroll
            for (int i = 0; i < 4; i++) xv[i] = xb[i * 16 * 16 + jq];
#pragma unroll
            for (int jm = 0; jm < 4; jm++) {
                uint4 c0 = cb[jm * 16 * 33 + jq * 2];
                uint4 c1 = cb[jm * 16 * 33 + jq * 2 + 1];
#pragma unroll
                for (int i = 0; i < 4; i++) {
                    __nv_bfloat162 l0 = __hfma2(asbf2(c0.x), asbf2(xv[i].x), asbf2(c0.y));
                    __nv_bfloat162 l1 = __hfma2(asbf2(c0.z), asbf2(xv[i].y), asbf2(c0.w));
                    __nv_bfloat162 l2 = __hfma2(asbf2(c1.x), asbf2(xv[i].z), asbf2(c1.y));
                    __nv_bfloat162 l3 = __hfma2(asbf2(c1.z), asbf2(xv[i].w), asbf2(c1.w));
                    prod[i][jm] = __hmul2(prod[i][jm],
                                          __hmul2(__hmul2(l0, l1), __hmul2(l2, l3)));
                }
            }
        }
        // merge: 64 d per accumulator (scaled x2: safe fp32 range)
#pragma unroll
        for (int i = 0; i < 4; i++)
#pragma unroll
            for (int jm = 0; jm < 4; jm++) {
                uint32_t u = asu32(prod[i][jm]);
                float hi = __uint_as_float(u & 0xFFFF0000u);
                float lo = __uint_as_float(u << 16);
                acc[i][jm] += __log2f(hi * lo);
            }
    }

    asm volatile("cp.async.wait_group 0;");
    __syncthreads();
    // combine tz halves through smem (stride 17 floats: no bank conflicts)
    float* sh = (float*)sm;
    const int tid256 = t & 255;
    if (tz == 1) {
#pragma unroll
        for (int i = 0; i < 4; i++)
#pragma unroll
            for (int jm = 0; jm < 4; jm++)
                sh[tid256 * 17 + i * 4 + jm] = acc[i][jm];
    }
    __syncthreads();
    if (tz == 0) {
#pragma unroll
        for (int i = 0; i < 4; i++)
#pragma unroll
            for (int jm = 0; jm < 4; jm++) {
                float a = acc[i][jm] + sh[tid256 * 17 + i * 4 + jm];
                g_comp[(size_t)(bBase + ty + 16 * i) * MM + (mBase + tx + 16 * jm)] = a;
            }
    }

    // ---- fused logsumexp: last CTA of this b-tile reduces its 64 batches ----
    __threadfence();
    __syncthreads();
    if (t == 0) sflag = atomicAdd(&g_cnt[blockIdx.x], 1);
    __syncthreads();
    if (sflag == 3) {
        __threadfence();
        const float LN2 = 0.69314718055994531f;
        int warp = t >> 5, lane = t & 31;
        const float4* lw4 = reinterpret_cast<const float4*>(g_logw) + lane * 2;
        float4 l0 = lw4[0], l1 = lw4[1];
#pragma unroll
        for (int bb = 0; bb < 4; bb++) {
            int b = bBase + warp * 4 + bb;
            const float4* cp4 = reinterpret_cast<const float4*>(g_comp + (size_t)b * MM) + lane * 2;
            float4 c0 = __ldcg(cp4), c1 = __ldcg(cp4 + 1);
            float v[8];
            v[0] = (c0.x - 1024.0f) * LN2 + l0.x;
            v[1] = (c0.y - 1024.0f) * LN2 + l0.y;
            v[2] = (c0.z - 1024.0f) * LN2 + l0.z;
            v[3] = (c0.w - 1024.0f) * LN2 + l0.w;
            v[4] = (c1.x - 1024.0f) * LN2 + l1.x;
            v[5] = (c1.y - 1024.0f) * LN2 + l1.y;
            v[6] = (c1.z - 1024.0f) * LN2 + l1.z;
            v[7] = (c1.w - 1024.0f) * LN2 + l1.w;
            float mx = v[0];
#pragma unroll
            for (int j = 1; j < 8; j++) mx = fmaxf(mx, v[j]);
#pragma unroll
            for (int o = 16; o > 0; o >>= 1) mx = fmaxf(mx, __shfl_xor_sync(0xFFFFFFFFu, mx, o));
            float s = 0.0f;
#pragma unroll
            for (int j = 0; j < 8; j++) s += __expf(v[j] - mx);
#pragma unroll
            for (int o = 16; o > 0; o >>= 1) s += __shfl_xor_sync(0xFFFFFFFFu, s, o);
            if (lane == 0) out[b] = mx + __logf(s);
        }
    }
}

extern "C" void kernel_launch(void* const* d_in, const int* in_sizes, int n_in,
                              void* d_out, int out_size) {
    const float* x = nullptr;
    const float* W = nullptr;
    const float* P = nullptr;
    for (int i = 0; i < n_in; i++) {
        if      (in_sizes[i] == BB * DD) x = (const float*)d_in[i];
        else if (in_sizes[i] == MM)      W = (const float*)d_in[i];
        else if (in_sizes[i] == MM * DD) P = (const float*)d_in[i];
    }

    prep_kernel<<<321, 256>>>(x, P, W);

    const int SMEM = 3 * (XSTG + CSTG) * 16;   // 150,528 bytes
    cudaFuncSetAttribute(main_kernel, cudaFuncAttributeMaxDynamicSharedMemorySize, SMEM);
    dim3 grid(BB / 64, MM / 64);
    main_kernel<<<grid, 512, SMEM>>>((float*)d_out);
}